// round 12
// baseline (speedup 1.0000x reference)
#include <cuda_runtime.h>
#include <cstdint>
#include <cmath>

// ---------------- problem constants ----------------
constexpr int cB = 128, cT = 128, cE = 1024, cH = 1024, cNH = 8, cA = 64;
constexpr int cKV = cNH * cA;          // 512
constexpr int BE  = cB * cE;           // 131072

// ---------------- persistent device scratch ----------------
__device__ float g_MUS [cT * BE];          // (T,B,E)
__device__ float g_SIGS[cT * BE];          // (T,B,E)
__device__ float g_S   [cT * BE];          // (T,B,E)
__device__ float g_X   [cB * 2048];        // [encs | context]
__device__ float g_H   [cB * cH];
__device__ float g_GIE [cB * 3072];        // encs @ W_ih[:, :E]^T (once)
__device__ float g_GI16[16][cB * 3072];    // ctx-half gi partials (ksplit16)
__device__ float g_GH8 [8][cB * 3072];     // gh partials (ksplit8)
__device__ float g_MSP [16][cB * cE];      // mu partials [0..7], sig partials [8..15]
__device__ float g_QP  [8][cB * cKV];      // q partials (ksplit8)
__device__ float g_U   [cB * cNH * cE];    // (b,h,e)

struct Ptrs { const float* w[17]; };
__device__ Ptrs g_ptr;

// ---------------- threefry2x32 (jax-exact bits) ----------------
__device__ __forceinline__ uint2 tf2x32(unsigned k0, unsigned k1, unsigned x0, unsigned x1) {
    unsigned k2 = k0 ^ k1 ^ 0x1BD11BDAu;
    x0 += k0; x1 += k1;
#define TFR(r) x0 += x1; x1 = __funnelshift_l(x1, x1, r); x1 ^= x0;
    TFR(13) TFR(15) TFR(26) TFR(6)   x0 += k1; x1 += k2 + 1u;
    TFR(17) TFR(29) TFR(16) TFR(24)  x0 += k2; x1 += k0 + 2u;
    TFR(13) TFR(15) TFR(26) TFR(6)   x0 += k0; x1 += k1 + 3u;
    TFR(17) TFR(29) TFR(16) TFR(24)  x0 += k1; x1 += k2 + 4u;
    TFR(13) TFR(15) TFR(26) TFR(6)   x0 += k2; x1 += k0 + 5u;
#undef TFR
    return make_uint2(x0, x1);
}
__device__ __forceinline__ uint2 step_key(int i) { return tf2x32(0u, 1234u, 0u, (unsigned)i); }

// bits -> N(0,1): jax _uniform + sqrt(2)*erf_inv (Giles poly), fast-log variant
__device__ __forceinline__ float tf_normal(unsigned bits) {
    float f = __uint_as_float((bits >> 9) | 0x3f800000u) - 1.0f;
    float u = fmaf(f, 2.0f, -0.99999994f);
    u = fmaxf(u, -0.99999994f);
    float w = -__logf(fmaf(-u, u, 1.0f));
    float p;
    if (w < 5.0f) {
        w -= 2.5f;
        p = 2.81022636e-08f;
        p = fmaf(p, w, 3.43273939e-07f);
        p = fmaf(p, w, -3.5233877e-06f);
        p = fmaf(p, w, -4.39150654e-06f);
        p = fmaf(p, w, 0.00021858087f);
        p = fmaf(p, w, -0.00125372503f);
        p = fmaf(p, w, -0.00417768164f);
        p = fmaf(p, w, 0.246640727f);
        p = fmaf(p, w, 1.50140941f);
    } else {
        w = sqrtf(w) - 3.0f;
        p = -0.000200214257f;
        p = fmaf(p, w, 0.000100950558f);
        p = fmaf(p, w, 0.00134934322f);
        p = fmaf(p, w, -0.00367342844f);
        p = fmaf(p, w, 0.00573950773f);
        p = fmaf(p, w, -0.0076224613f);
        p = fmaf(p, w, 0.00943887047f);
        p = fmaf(p, w, 1.00167406f);
        p = fmaf(p, w, 2.83297682f);
    }
    return 1.4142135623730951f * (p * u);
}
__device__ __forceinline__ float eps_at(unsigned k0, unsigned k1, unsigned idx) {
    uint2 r = tf2x32(k0, k1, 0u, idx);
    return tf_normal(r.x ^ r.y);
}
__device__ __forceinline__ float softplusf(float x) {
    return fmaxf(x, 0.f) + log1pf(expf(-fabsf(x)));
}

// ---------------- setup + init ----------------
__global__ void k_setup(Ptrs p) { g_ptr = p; }
__global__ void k_init() {
    int idx = blockIdx.x * 256 + threadIdx.x;
    const float* encs = g_ptr.w[0];
    if (idx < cB * 2048) {
        int b = idx >> 11, c = idx & 2047;
        g_X[idx] = (c < cE) ? encs[b * cE + c] : 0.f;
    }
    if (idx < cB * cH) g_H[idx] = 0.f;
    if (idx < 8 * cB * 3072) reinterpret_cast<float*>(g_GH8)[idx] = 0.f;  // h0=0 -> gh=0
}

// ---- SGEMM: BM=128, BN=64, BK=8, 128 thr, 8x8 microtile, dbl-buf ----------
enum { SEL_EB = 0, SEL_GIC, SEL_HMS, SEL_QB, SEL_UB };

struct GD {
    const float* A; const float* Bm; float* C; const float* qbias;
    int lda, ldb, ldc, K, transB, qsum;
};

__device__ __forceinline__ GD get_desc(int sel, int y, int z, int i) {
    GD d; d.qbias = nullptr; d.transB = 0; d.qsum = 0;
    switch (sel) {
    case SEL_EB:   // encs @ W_ih[:, :E]^T ; y in [0,48)
        d.A = g_ptr.w[0]; d.lda = 1024; d.K = 1024;
        d.Bm = g_ptr.w[1] + (size_t)(y * 64) * 2048; d.ldb = 2048; d.transB = 1;
        d.C = g_GIE + y * 64; d.ldc = 3072; break;
    case SEL_GIC:  // ctx @ W_ih[:, E:]^T ; ksplit16 (z), y in [0,48)
        d.A = g_X + 1024 + z * 64; d.lda = 2048; d.K = 64;
        d.Bm = g_ptr.w[1] + 1024 + z * 64 + (size_t)(y * 64) * 2048; d.ldb = 2048; d.transB = 1;
        d.C = g_GI16[z] + y * 64; d.ldc = 3072; break;
    case SEL_HMS:  // h @ [W_hh^T | W_mu | W_sig] ; ksplit8 (z), y in [0,80)
        d.A = g_H + z * 128; d.lda = 1024; d.K = 128;
        if (y < 48) {
            d.Bm = g_ptr.w[2] + z * 128 + (size_t)(y * 64) * 1024; d.ldb = 1024; d.transB = 1;
            d.C = g_GH8[z] + y * 64; d.ldc = 3072;
        } else if (y < 64) {
            int yy = y - 48;
            d.Bm = g_ptr.w[5] + (size_t)(z * 128) * 1024 + yy * 64; d.ldb = 1024;
            d.C = g_MSP[z] + yy * 64; d.ldc = 1024;
        } else {
            int yy = y - 64;
            d.Bm = g_ptr.w[7] + (size_t)(z * 128) * 1024 + yy * 64; d.ldb = 1024;
            d.C = g_MSP[8 + z] + yy * 64; d.ldc = 1024;
        }
        break;
    case SEL_QB:   // s_i @ W_q ; ksplit8 (z), y in [0,8)
        d.A = g_S + (size_t)i * BE + z * 128; d.lda = 1024; d.K = 128;
        d.Bm = g_ptr.w[9] + (size_t)(z * 128) * 512 + y * 64; d.ldb = 512;
        d.C = g_QP[z] + y * 64; d.ldc = 512; break;
    default:       // SEL_UB: u_h = (sum 8 q-partials + b_q) @ W_k_h^T ; z=head, y in [0,16)
        d.qsum = 1;
        d.A = g_QP[0] + z * 64; d.lda = 512; d.K = 64;
        d.qbias = g_ptr.w[10] + z * 64;
        d.Bm = g_ptr.w[11] + z * 64 + (size_t)(y * 64) * 512; d.ldb = 512; d.transB = 1;
        d.C = g_U + z * 1024 + y * 64; d.ldc = 8192; break;
    }
    return d;
}

__global__ __launch_bounds__(128) void k_gemm(int sel, int i) {
    GD d = get_desc(sel, blockIdx.y, blockIdx.z, i);

    __shared__ __align__(16) float As[2][8][132];
    __shared__ __align__(16) float Bs[2][8][68];

    int tid = threadIdx.x;
    int tx = tid & 7, ty = tid >> 3;

    float acc[8][8];
#pragma unroll
    for (int r = 0; r < 8; r++)
#pragma unroll
        for (int c = 0; c < 8; c++) acc[r][c] = 0.f;

    float4 va[2]; float4 vb;
    int arow = tid >> 1, akc = (tid & 1) << 2;
    int bkk = tid >> 4, bnc = (tid & 15) << 2;
    int bnn = tid >> 1, bkc = (tid & 1) << 2;

    auto loadT = [&](int k0) {
#pragma unroll
        for (int r = 0; r < 2; r++) {
            const float* ap = d.A + (size_t)(arow + r * 64) * d.lda + k0 + akc;
            if (!d.qsum) {
                va[r] = *reinterpret_cast<const float4*>(ap);
            } else {
                va[r] = *reinterpret_cast<const float4*>(d.qbias + k0 + akc);
#pragma unroll
                for (int p = 0; p < 8; p++) {
                    float4 v = *reinterpret_cast<const float4*>(ap + p * 65536);
                    va[r].x += v.x; va[r].y += v.y; va[r].z += v.z; va[r].w += v.w;
                }
            }
        }
        if (!d.transB)
            vb = *reinterpret_cast<const float4*>(d.Bm + (size_t)(k0 + bkk) * d.ldb + bnc);
        else
            vb = *reinterpret_cast<const float4*>(d.Bm + (size_t)bnn * d.ldb + k0 + bkc);
    };
    auto storeT = [&](int cur) {
#pragma unroll
        for (int r = 0; r < 2; r++) {
            int row = arow + r * 64;
            As[cur][akc + 0][row] = va[r].x; As[cur][akc + 1][row] = va[r].y;
            As[cur][akc + 2][row] = va[r].z; As[cur][akc + 3][row] = va[r].w;
        }
        if (!d.transB) {
            *reinterpret_cast<float4*>(&Bs[cur][bkk][bnc]) = vb;
        } else {
            Bs[cur][bkc + 0][bnn] = vb.x; Bs[cur][bkc + 1][bnn] = vb.y;
            Bs[cur][bkc + 2][bnn] = vb.z; Bs[cur][bkc + 3][bnn] = vb.w;
        }
    };

    int nt = d.K >> 3;
    loadT(0);
    int cur = 0;
    for (int t = 0; t < nt; t++) {
        storeT(cur);
        __syncthreads();
        if (t + 1 < nt) loadT((t + 1) << 3);
#pragma unroll
        for (int kk = 0; kk < 8; kk++) {
            float4 a0 = *reinterpret_cast<const float4*>(&As[cur][kk][ty * 8]);
            float4 a1 = *reinterpret_cast<const float4*>(&As[cur][kk][ty * 8 + 4]);
            float4 b0 = *reinterpret_cast<const float4*>(&Bs[cur][kk][tx * 8]);
            float4 b1 = *reinterpret_cast<const float4*>(&Bs[cur][kk][tx * 8 + 4]);
            float af[8] = {a0.x, a0.y, a0.z, a0.w, a1.x, a1.y, a1.z, a1.w};
            float bf[8] = {b0.x, b0.y, b0.z, b0.w, b1.x, b1.y, b1.z, b1.w};
#pragma unroll
            for (int r = 0; r < 8; r++)
#pragma unroll
                for (int c = 0; c < 8; c++) acc[r][c] = fmaf(af[r], bf[c], acc[r][c]);
        }
        cur ^= 1;
    }

#pragma unroll
    for (int r = 0; r < 8; r++) {
        int m = ty * 8 + r;
        float* cp = d.C + (size_t)m * d.ldc + tx * 8;
        *reinterpret_cast<float4*>(cp)     = make_float4(acc[r][0], acc[r][1], acc[r][2], acc[r][3]);
        *reinterpret_cast<float4*>(cp + 4) = make_float4(acc[r][4], acc[r][5], acc[r][6], acc[r][7]);
    }
}

// ---------------- GRU gate combine (sums GI16 x16 + GH8 x8 partials) -------
__global__ void k_combine() {
    int idx = blockIdx.x * 256 + threadIdx.x;
    int b = idx >> 10, m = idx & 1023;
    const float* b_ih = g_ptr.w[3];
    const float* b_hh = g_ptr.w[4];
    int o = b * 3072;
    float ir = g_GIE[o + m] + b_ih[m];
    float iz = g_GIE[o + m + 1024] + b_ih[m + 1024];
    float in = g_GIE[o + m + 2048] + b_ih[m + 2048];
#pragma unroll
    for (int p = 0; p < 16; p++) {
        ir += g_GI16[p][o + m];
        iz += g_GI16[p][o + m + 1024];
        in += g_GI16[p][o + m + 2048];
    }
    float hr = b_hh[m], hz = b_hh[m + 1024], hn = b_hh[m + 2048];
#pragma unroll
    for (int p = 0; p < 8; p++) {
        hr += g_GH8[p][o + m];
        hz += g_GH8[p][o + m + 1024];
        hn += g_GH8[p][o + m + 2048];
    }
    float r = 1.f / (1.f + expf(-(ir + hr)));
    float z = 1.f / (1.f + expf(-(iz + hz)));
    float n = tanhf(fmaf(r, hn, in));
    float h = g_H[idx];
    g_H[idx] = fmaf(z, h - n, n);
}

// ---- gen_s: finalize row i + sample; 8 elems/thread for threefry ILP ------
__global__ __launch_bounds__(256) void k_gen_s(int i) {
    int j  = blockIdx.x >> 6;
    int b  = ((blockIdx.x & 63) << 1) + (threadIdx.x >> 7);
    int e  = (threadIdx.x & 127) << 3;
    uint2 kk = step_key(i);
    size_t off = (size_t)(j * cB + b) * cE + e;
    float4 mu0, mu1, sg0, sg1;
    if (j == i) {
        int q = b * 1024 + e;
        mu0 = *reinterpret_cast<const float4*>(g_ptr.w[6] + e);
        mu1 = *reinterpret_cast<const float4*>(g_ptr.w[6] + e + 4);
        sg0 = *reinterpret_cast<const float4*>(g_ptr.w[8] + e);
        sg1 = *reinterpret_cast<const float4*>(g_ptr.w[8] + e + 4);
#pragma unroll
        for (int p = 0; p < 8; p++) {
            float4 m0 = *reinterpret_cast<const float4*>(&g_MSP[p][q]);
            float4 m1 = *reinterpret_cast<const float4*>(&g_MSP[p][q + 4]);
            float4 s0 = *reinterpret_cast<const float4*>(&g_MSP[p + 8][q]);
            float4 s1 = *reinterpret_cast<const float4*>(&g_MSP[p + 8][q + 4]);
            mu0.x += m0.x; mu0.y += m0.y; mu0.z += m0.z; mu0.w += m0.w;
            mu1.x += m1.x; mu1.y += m1.y; mu1.z += m1.z; mu1.w += m1.w;
            sg0.x += s0.x; sg0.y += s0.y; sg0.z += s0.z; sg0.w += s0.w;
            sg1.x += s1.x; sg1.y += s1.y; sg1.z += s1.z; sg1.w += s1.w;
        }
        sg0.x = softplusf(sg0.x); sg0.y = softplusf(sg0.y);
        sg0.z = softplusf(sg0.z); sg0.w = softplusf(sg0.w);
        sg1.x = softplusf(sg1.x); sg1.y = softplusf(sg1.y);
        sg1.z = softplusf(sg1.z); sg1.w = softplusf(sg1.w);
        *reinterpret_cast<float4*>(g_MUS + off) = mu0;
        *reinterpret_cast<float4*>(g_MUS + off + 4) = mu1;
        *reinterpret_cast<float4*>(g_SIGS + off) = sg0;
        *reinterpret_cast<float4*>(g_SIGS + off + 4) = sg1;
    } else {
        mu0 = *reinterpret_cast<const float4*>(g_MUS + off);
        mu1 = *reinterpret_cast<const float4*>(g_MUS + off + 4);
        sg0 = *reinterpret_cast<const float4*>(g_SIGS + off);
        sg1 = *reinterpret_cast<const float4*>(g_SIGS + off + 4);
    }
    unsigned p = (unsigned)((b * cT + j) * cE + e);
    float ep[8];
#pragma unroll
    for (int u = 0; u < 8; u++) ep[u] = eps_at(kk.x, kk.y, p + u);
    float4 s0, s1;
    s0.x = fmaf(ep[0], sg0.x, mu0.x); s0.y = fmaf(ep[1], sg0.y, mu0.y);
    s0.z = fmaf(ep[2], sg0.z, mu0.z); s0.w = fmaf(ep[3], sg0.w, mu0.w);
    s1.x = fmaf(ep[4], sg1.x, mu1.x); s1.y = fmaf(ep[5], sg1.y, mu1.y);
    s1.z = fmaf(ep[6], sg1.z, mu1.z); s1.w = fmaf(ep[7], sg1.w, mu1.w);
    *reinterpret_cast<float4*>(g_S + off) = s0;
    *reinterpret_cast<float4*>(g_S + off + 4) = s1;
}

// finalize-only (step 127)
__global__ __launch_bounds__(256) void k_msfix(int i) {
    int b = blockIdx.x;
    int e = threadIdx.x << 2;
    int q = b * 1024 + e;
    size_t off = (size_t)(i * cB + b) * cE + e;
    float4 mu = *reinterpret_cast<const float4*>(g_ptr.w[6] + e);
    float4 sg = *reinterpret_cast<const float4*>(g_ptr.w[8] + e);
#pragma unroll
    for (int p = 0; p < 8; p++) {
        float4 mp = *reinterpret_cast<const float4*>(&g_MSP[p][q]);
        float4 sp = *reinterpret_cast<const float4*>(&g_MSP[p + 8][q]);
        mu.x += mp.x; mu.y += mp.y; mu.z += mp.z; mu.w += mp.w;
        sg.x += sp.x; sg.y += sp.y; sg.z += sp.z; sg.w += sp.w;
    }
    sg.x = softplusf(sg.x); sg.y = softplusf(sg.y);
    sg.z = softplusf(sg.z); sg.w = softplusf(sg.w);
    *reinterpret_cast<float4*>(g_MUS + off) = mu;
    *reinterpret_cast<float4*>(g_SIGS + off) = sg;
}

// ---------------- mega attention: 2 b's per block, 64 blocks, 512 threads ---
__global__ __launch_bounds__(512) void k_attn(int i) {
    extern __shared__ float sm[];
    float* zs  = sm;            // 16384 floats (z, pass2+)
    float* w_s = sm + 16384;    // 2048 floats
    float* s_st = sm + 18432;   // 8192 floats: [bl][jr][1024]
    int bb = blockIdx.x;
    int nj = i + 1;
    int tid = threadIdx.x;
    int w = tid >> 5, l = tid & 31;
    int blw = w >> 3, hw = w & 7;

    // ---- pass 1: scores; u in registers, 4 j-rows staged per round ----
    {
        float4 ureg[8];
        const float4* up = reinterpret_cast<const float4*>(
            g_U + (size_t)(bb * 2 + blw) * 8192 + hw * 1024);
#pragma unroll
        for (int k = 0; k < 8; k++) ureg[k] = up[l + 32 * k];

        for (int j0 = 0; j0 < nj; j0 += 4) {
#pragma unroll
            for (int r = 0; r < 4; r++) {
                int idx = tid + r * 512;
                int row = idx >> 8;
                int bl = row >> 2, jr = row & 3;
                int j = j0 + jr;
                if (j < nj)
                    reinterpret_cast<float4*>(s_st)[idx] =
                        reinterpret_cast<const float4*>(
                            g_S + (size_t)(j * cB + bb * 2 + bl) * cE)[idx & 255];
            }
            __syncthreads();
            const float4* sbase = reinterpret_cast<const float4*>(s_st + blw * 4096);
#pragma unroll
            for (int jr = 0; jr < 4; jr++) {
                int j = j0 + jr;
                if (j < nj) {
                    const float4* sv4 = sbase + jr * 256;
                    float acc = 0.f;
#pragma unroll
                    for (int k = 0; k < 8; k++) {
                        float4 sv = sv4[l + 32 * k];
                        acc = fmaf(sv.x, ureg[k].x, acc); acc = fmaf(sv.y, ureg[k].y, acc);
                        acc = fmaf(sv.z, ureg[k].z, acc); acc = fmaf(sv.w, ureg[k].w, acc);
                    }
#pragma unroll
                    for (int o = 16; o; o >>= 1) acc += __shfl_xor_sync(0xffffffffu, acc, o);
                    if (l == 0) w_s[w * 128 + j] = acc * 0.125f;
                }
            }
            __syncthreads();
        }
    }

    // ---- softmax per (bl,h) combo = warp ----
    {
        float v[4];
#pragma unroll
        for (int cc = 0; cc < 4; cc++) {
            int j = l + 32 * cc;
            v[cc] = (j < nj) ? w_s[w * 128 + j] : -3.0e38f;
        }
        float m = fmaxf(fmaxf(v[0], v[1]), fmaxf(v[2], v[3]));
#pragma unroll
        for (int o = 16; o; o >>= 1) m = fmaxf(m, __shfl_xor_sync(0xffffffffu, m, o));
        float e[4], sum = 0.f;
#pragma unroll
        for (int cc = 0; cc < 4; cc++) {
            int j = l + 32 * cc;
            e[cc] = (j < nj) ? expf(v[cc] - m) : 0.f;
            sum += e[cc];
        }
#pragma unroll
        for (int o = 16; o; o >>= 1) sum += __shfl_xor_sync(0xffffffffu, sum, o);
        float inv = 1.f / sum;
#pragma unroll
        for (int cc = 0; cc < 4; cc++) {
            int j = l + 32 * cc;
            if (j < nj) w_s[w * 128 + j] = e[cc] * inv;
        }
    }
    __syncthreads();

    // ---- pass 2: z[bl][h][e] = sum_j w * s ----
    {
        int bl = tid >> 8;
        int e0 = (tid & 255) << 2;
        int b = bb * 2 + bl;
        float za[8][4];
#pragma unroll
        for (int h = 0; h < 8; h++)
#pragma unroll
            for (int u = 0; u < 4; u++) za[h][u] = 0.f;
        for (int j = 0; j < nj; j++) {
            float4 sv = *reinterpret_cast<const float4*>(g_S + (size_t)(j * cB + b) * cE + e0);
#pragma unroll
            for (int h = 0; h < 8; h++) {
                float wj = w_s[(bl * 8 + h) * 128 + j];
                za[h][0] = fmaf(wj, sv.x, za[h][0]);
                za[h][1] = fmaf(wj, sv.y, za[h][1]);
                za[h][2] = fmaf(wj, sv.z, za[h][2]);
                za[h][3] = fmaf(wj, sv.w, za[h][3]);
            }
        }
#pragma unroll
        for (int h = 0; h < 8; h++)
            *reinterpret_cast<float4*>(zs + bl * 8192 + h * 1024 + e0) =
                make_float4(za[h][0], za[h][1], za[h][2], za[h][3]);
    }
    __syncthreads();

    // ---- pass 3: ctx ----
    {
        int bl = tid >> 8;
        int c2 = (tid & 255) << 1;
        int h = c2 >> 6;
        const float* zrow = zs + bl * 8192 + h * 1024;
        const float* Wv = g_ptr.w[13];
        float a0 = 0.f, a1 = 0.f;
        for (int e = 0; e < 1024; e++) {
            float zv = zrow[e];
            float2 wv = *reinterpret_cast<const float2*>(Wv + (size_t)e * 512 + c2);
            a0 = fmaf(zv, wv.x, a0); a1 = fmaf(zv, wv.y, a1);
        }
        float2 bv2 = *reinterpret_cast<const float2*>(g_ptr.w[14] + c2);
        __syncthreads();
        *reinterpret_cast<float2*>(w_s + bl * 512 + c2) = make_float2(a0 + bv2.x, a1 + bv2.y);
    }
    __syncthreads();

    // ---- pass 4: out-proj into X ----
    {
        int bl = tid >> 8;
        int e0 = (tid & 255) << 2;
        const float* Wo = g_ptr.w[15];
        float a0 = 0.f, a1 = 0.f, a2 = 0.f, a3 = 0.f;
        for (int c = 0; c < 512; c++) {
            float cv = w_s[bl * 512 + c];
            float4 wo = *reinterpret_cast<const float4*>(Wo + (size_t)c * 1024 + e0);
            a0 = fmaf(cv, wo.x, a0); a1 = fmaf(cv, wo.y, a1);
            a2 = fmaf(cv, wo.z, a2); a3 = fmaf(cv, wo.w, a3);
        }
        float4 bo4 = *reinterpret_cast<const float4*>(g_ptr.w[16] + e0);
        *reinterpret_cast<float4*>(g_X + (bb * 2 + bl) * 2048 + 1024 + e0) =
            make_float4(a0 + bo4.x, a1 + bo4.y, a2 + bo4.z, a3 + bo4.w);
    }
}

// ---------------- final output (B,T,E): step-127 noise ----------------
__global__ __launch_bounds__(256) void k_genout(float* __restrict__ out) {
    int j = blockIdx.x >> 6;
    int b = ((blockIdx.x & 63) << 1) + (threadIdx.x >> 7);
    int e = (threadIdx.x & 127) << 3;
    uint2 kk = step_key(cT - 1);
    size_t off = (size_t)(j * cB + b) * cE + e;
    float4 mu0 = *reinterpret_cast<const float4*>(g_MUS + off);
    float4 mu1 = *reinterpret_cast<const float4*>(g_MUS + off + 4);
    float4 sg0 = *reinterpret_cast<const float4*>(g_SIGS + off);
    float4 sg1 = *reinterpret_cast<const float4*>(g_SIGS + off + 4);
    unsigned p = (unsigned)((b * cT + j) * cE + e);
    float ep[8];
#pragma unroll
    for (int u = 0; u < 8; u++) ep[u] = eps_at(kk.x, kk.y, p + u);
    float4 s0, s1;
    s0.x = fmaf(ep[0], sg0.x, mu0.x); s0.y = fmaf(ep[1], sg0.y, mu0.y);
    s0.z = fmaf(ep[2], sg0.z, mu0.z); s0.w = fmaf(ep[3], sg0.w, mu0.w);
    s1.x = fmaf(ep[4], sg1.x, mu1.x); s1.y = fmaf(ep[5], sg1.y, mu1.y);
    s1.z = fmaf(ep[6], sg1.z, mu1.z); s1.w = fmaf(ep[7], sg1.w, mu1.w);
    *reinterpret_cast<float4*>(out + p) = s0;
    *reinterpret_cast<float4*>(out + p + 4) = s1;
}

// ---------------- host side ----------------
extern "C" void kernel_launch(void* const* d_in, const int* in_sizes, int n_in,
                              void* d_out, int out_size) {
    Ptrs P;
    for (int k = 0; k < 17; k++) P.w[k] = (const float*)d_in[k];
    float* out = (float*)d_out;

    constexpr int ATTN_SMEM = (16384 + 2048 + 8192) * 4;   // 106496 B
    cudaFuncSetAttribute(k_attn, cudaFuncAttributeMaxDynamicSharedMemorySize, ATTN_SMEM);

    k_setup<<<1, 1>>>(P);
    k_init<<<12288, 256>>>();
    k_gemm<<<dim3(1, 48, 1), 128>>>(SEL_EB, 0);       // encs half of gi (once)

    for (int i = 0; i < cT; i++) {
        k_gemm<<<dim3(1, 48, 16), 128>>>(SEL_GIC, i); // ctx-half gi, ksplit16
        k_combine<<<512, 256>>>();                    // h update (uses prev GH8)
        k_gemm<<<dim3(1, 80, 8), 128>>>(SEL_HMS, i);  // h@[W_hh|W_mu|W_sig], ksplit8

        if (i < cT - 1) {
            k_gen_s<<<(i + 1) * 64, 256>>>(i);        // finalize mu/sig row i + sample S
            k_gemm<<<dim3(1, 8, 8), 128>>>(SEL_QB, i);    // q partials, ksplit8
            k_gemm<<<dim3(1, 16, 8), 128>>>(SEL_UB, i);   // u per head (sums 8 q)
            k_attn<<<64, 512, ATTN_SMEM>>>(i);
        } else {
            k_msfix<<<cB, 256>>>(i);
        }
    }

    k_genout<<<cT * 64, 256>>>(out);
}

// round 14
// speedup vs baseline: 1.0908x; 1.0908x over previous
#include <cuda_runtime.h>
#include <cstdint>
#include <cmath>

// ---------------- problem constants ----------------
constexpr int cB = 128, cT = 128, cE = 1024, cH = 1024, cNH = 8, cA = 64;
constexpr int cKV = cNH * cA;          // 512
constexpr int BE  = cB * cE;           // 131072

// ---------------- persistent device scratch ----------------
__device__ float g_MUS [cT * BE];          // (T,B,E)
__device__ float g_SIGS[cT * BE];          // (T,B,E)
__device__ float g_S   [cT * BE];          // (T,B,E)
__device__ float g_X   [cB * 2048];        // [encs | context]
__device__ float g_H   [cB * cH];
__device__ float g_GIE [cB * 3072];        // encs @ W_ih[:, :E]^T (once)
__device__ float g_GI8 [8][cB * 3072];     // ctx-half gi partials (ksplit8)
__device__ float g_GH4 [4][cB * 3072];     // gh partials (ksplit4)
__device__ float g_MSP [8][cB * cE];       // mu partials [0..3], sig partials [4..7]
__device__ float g_QP  [4][cB * cKV];      // q partials (ksplit4)
__device__ float g_U   [cB * cNH * cE];    // (b,h,e)

struct Ptrs { const float* w[17]; };
__device__ Ptrs g_ptr;

// ---------------- threefry2x32 (jax-exact bits) ----------------
__device__ __forceinline__ uint2 tf2x32(unsigned k0, unsigned k1, unsigned x0, unsigned x1) {
    unsigned k2 = k0 ^ k1 ^ 0x1BD11BDAu;
    x0 += k0; x1 += k1;
#define TFR(r) x0 += x1; x1 = __funnelshift_l(x1, x1, r); x1 ^= x0;
    TFR(13) TFR(15) TFR(26) TFR(6)   x0 += k1; x1 += k2 + 1u;
    TFR(17) TFR(29) TFR(16) TFR(24)  x0 += k2; x1 += k0 + 2u;
    TFR(13) TFR(15) TFR(26) TFR(6)   x0 += k0; x1 += k1 + 3u;
    TFR(17) TFR(29) TFR(16) TFR(24)  x0 += k1; x1 += k2 + 4u;
    TFR(13) TFR(15) TFR(26) TFR(6)   x0 += k2; x1 += k0 + 5u;
#undef TFR
    return make_uint2(x0, x1);
}
__device__ __forceinline__ uint2 step_key(int i) { return tf2x32(0u, 1234u, 0u, (unsigned)i); }

// bits -> N(0,1): jax _uniform + sqrt(2)*erf_inv (Giles poly), fast-log variant
__device__ __forceinline__ float tf_normal(unsigned bits) {
    float f = __uint_as_float((bits >> 9) | 0x3f800000u) - 1.0f;
    float u = fmaf(f, 2.0f, -0.99999994f);
    u = fmaxf(u, -0.99999994f);
    float w = -__logf(fmaf(-u, u, 1.0f));
    float p;
    if (w < 5.0f) {
        w -= 2.5f;
        p = 2.81022636e-08f;
        p = fmaf(p, w, 3.43273939e-07f);
        p = fmaf(p, w, -3.5233877e-06f);
        p = fmaf(p, w, -4.39150654e-06f);
        p = fmaf(p, w, 0.00021858087f);
        p = fmaf(p, w, -0.00125372503f);
        p = fmaf(p, w, -0.00417768164f);
        p = fmaf(p, w, 0.246640727f);
        p = fmaf(p, w, 1.50140941f);
    } else {
        w = sqrtf(w) - 3.0f;
        p = -0.000200214257f;
        p = fmaf(p, w, 0.000100950558f);
        p = fmaf(p, w, 0.00134934322f);
        p = fmaf(p, w, -0.00367342844f);
        p = fmaf(p, w, 0.00573950773f);
        p = fmaf(p, w, -0.0076224613f);
        p = fmaf(p, w, 0.00943887047f);
        p = fmaf(p, w, 1.00167406f);
        p = fmaf(p, w, 2.83297682f);
    }
    return 1.4142135623730951f * (p * u);
}
__device__ __forceinline__ float eps_at(unsigned k0, unsigned k1, unsigned idx) {
    uint2 r = tf2x32(k0, k1, 0u, idx);
    return tf_normal(r.x ^ r.y);
}
__device__ __forceinline__ float softplusf(float x) {
    return fmaxf(x, 0.f) + log1pf(expf(-fabsf(x)));
}

// ---------------- setup + init ----------------
__global__ void k_setup(Ptrs p) { g_ptr = p; }
__global__ void k_init() {
    int idx = blockIdx.x * 256 + threadIdx.x;
    const float* encs = g_ptr.w[0];
    if (idx < cB * 2048) {
        int b = idx >> 11, c = idx & 2047;
        g_X[idx] = (c < cE) ? encs[b * cE + c] : 0.f;
    }
    if (idx < cB * cH) g_H[idx] = 0.f;
    if (idx < 4 * cB * 3072) reinterpret_cast<float*>(g_GH4)[idx] = 0.f;  // h0=0 -> gh=0
}

// ---- SGEMM (R11 config): BM=128, BN=64, BK=8, 128 thr, 8x8, dbl-buf -------
enum { SEL_EB = 0, SEL_GIC, SEL_HMS, SEL_QB, SEL_UB };

struct GD {
    const float* A; const float* Bm; float* C; const float* qbias;
    int lda, ldb, ldc, K, transB, qsum;
};

__device__ __forceinline__ GD get_desc(int sel, int y, int z, int i) {
    GD d; d.qbias = nullptr; d.transB = 0; d.qsum = 0;
    switch (sel) {
    case SEL_EB:   // encs @ W_ih[:, :E]^T ; y in [0,48)
        d.A = g_ptr.w[0]; d.lda = 1024; d.K = 1024;
        d.Bm = g_ptr.w[1] + (size_t)(y * 64) * 2048; d.ldb = 2048; d.transB = 1;
        d.C = g_GIE + y * 64; d.ldc = 3072; break;
    case SEL_GIC:  // ctx @ W_ih[:, E:]^T ; ksplit8 (z), y in [0,48)
        d.A = g_X + 1024 + z * 128; d.lda = 2048; d.K = 128;
        d.Bm = g_ptr.w[1] + 1024 + z * 128 + (size_t)(y * 64) * 2048; d.ldb = 2048; d.transB = 1;
        d.C = g_GI8[z] + y * 64; d.ldc = 3072; break;
    case SEL_HMS:  // h @ [W_hh^T | W_mu | W_sig] ; ksplit4 (z), y in [0,80)
        d.A = g_H + z * 256; d.lda = 1024; d.K = 256;
        if (y < 48) {
            d.Bm = g_ptr.w[2] + z * 256 + (size_t)(y * 64) * 1024; d.ldb = 1024; d.transB = 1;
            d.C = g_GH4[z] + y * 64; d.ldc = 3072;
        } else if (y < 64) {
            int yy = y - 48;
            d.Bm = g_ptr.w[5] + (size_t)(z * 256) * 1024 + yy * 64; d.ldb = 1024;
            d.C = g_MSP[z] + yy * 64; d.ldc = 1024;
        } else {
            int yy = y - 64;
            d.Bm = g_ptr.w[7] + (size_t)(z * 256) * 1024 + yy * 64; d.ldb = 1024;
            d.C = g_MSP[4 + z] + yy * 64; d.ldc = 1024;
        }
        break;
    case SEL_QB:   // s_i @ W_q ; ksplit4 (z), y in [0,8)
        d.A = g_S + (size_t)i * BE + z * 256; d.lda = 1024; d.K = 256;
        d.Bm = g_ptr.w[9] + (size_t)(z * 256) * 512 + y * 64; d.ldb = 512;
        d.C = g_QP[z] + y * 64; d.ldc = 512; break;
    default:       // SEL_UB: u_h = (sum 4 q-partials + b_q) @ W_k_h^T ; z=head, y in [0,16)
        d.qsum = 1;
        d.A = g_QP[0] + z * 64; d.lda = 512; d.K = 64;
        d.qbias = g_ptr.w[10] + z * 64;
        d.Bm = g_ptr.w[11] + z * 64 + (size_t)(y * 64) * 512; d.ldb = 512; d.transB = 1;
        d.C = g_U + z * 1024 + y * 64; d.ldc = 8192; break;
    }
    return d;
}

__global__ __launch_bounds__(128) void k_gemm(int sel, int i) {
    GD d = get_desc(sel, blockIdx.y, blockIdx.z, i);

    __shared__ __align__(16) float As[2][8][132];
    __shared__ __align__(16) float Bs[2][8][68];

    int tid = threadIdx.x;
    int tx = tid & 7, ty = tid >> 3;

    float acc[8][8];
#pragma unroll
    for (int r = 0; r < 8; r++)
#pragma unroll
        for (int c = 0; c < 8; c++) acc[r][c] = 0.f;

    float4 va[2]; float4 vb;
    int arow = tid >> 1, akc = (tid & 1) << 2;
    int bkk = tid >> 4, bnc = (tid & 15) << 2;
    int bnn = tid >> 1, bkc = (tid & 1) << 2;

    auto loadT = [&](int k0) {
#pragma unroll
        for (int r = 0; r < 2; r++) {
            const float* ap = d.A + (size_t)(arow + r * 64) * d.lda + k0 + akc;
            if (!d.qsum) {
                va[r] = *reinterpret_cast<const float4*>(ap);
            } else {
                float4 v0 = *reinterpret_cast<const float4*>(ap);
                float4 v1 = *reinterpret_cast<const float4*>(ap + 65536);
                float4 v2 = *reinterpret_cast<const float4*>(ap + 131072);
                float4 v3 = *reinterpret_cast<const float4*>(ap + 196608);
                float4 bb = *reinterpret_cast<const float4*>(d.qbias + k0 + akc);
                va[r].x = v0.x + v1.x + v2.x + v3.x + bb.x;
                va[r].y = v0.y + v1.y + v2.y + v3.y + bb.y;
                va[r].z = v0.z + v1.z + v2.z + v3.z + bb.z;
                va[r].w = v0.w + v1.w + v2.w + v3.w + bb.w;
            }
        }
        if (!d.transB)
            vb = *reinterpret_cast<const float4*>(d.Bm + (size_t)(k0 + bkk) * d.ldb + bnc);
        else
            vb = *reinterpret_cast<const float4*>(d.Bm + (size_t)bnn * d.ldb + k0 + bkc);
    };
    auto storeT = [&](int cur) {
#pragma unroll
        for (int r = 0; r < 2; r++) {
            int row = arow + r * 64;
            As[cur][akc + 0][row] = va[r].x; As[cur][akc + 1][row] = va[r].y;
            As[cur][akc + 2][row] = va[r].z; As[cur][akc + 3][row] = va[r].w;
        }
        if (!d.transB) {
            *reinterpret_cast<float4*>(&Bs[cur][bkk][bnc]) = vb;
        } else {
            Bs[cur][bkc + 0][bnn] = vb.x; Bs[cur][bkc + 1][bnn] = vb.y;
            Bs[cur][bkc + 2][bnn] = vb.z; Bs[cur][bkc + 3][bnn] = vb.w;
        }
    };

    int nt = d.K >> 3;
    loadT(0);
    int cur = 0;
    for (int t = 0; t < nt; t++) {
        storeT(cur);
        __syncthreads();
        if (t + 1 < nt) loadT((t + 1) << 3);
#pragma unroll
        for (int kk = 0; kk < 8; kk++) {
            float4 a0 = *reinterpret_cast<const float4*>(&As[cur][kk][ty * 8]);
            float4 a1 = *reinterpret_cast<const float4*>(&As[cur][kk][ty * 8 + 4]);
            float4 b0 = *reinterpret_cast<const float4*>(&Bs[cur][kk][tx * 8]);
            float4 b1 = *reinterpret_cast<const float4*>(&Bs[cur][kk][tx * 8 + 4]);
            float af[8] = {a0.x, a0.y, a0.z, a0.w, a1.x, a1.y, a1.z, a1.w};
            float bf[8] = {b0.x, b0.y, b0.z, b0.w, b1.x, b1.y, b1.z, b1.w};
#pragma unroll
            for (int r = 0; r < 8; r++)
#pragma unroll
                for (int c = 0; c < 8; c++) acc[r][c] = fmaf(af[r], bf[c], acc[r][c]);
        }
        cur ^= 1;
    }

#pragma unroll
    for (int r = 0; r < 8; r++) {
        int m = ty * 8 + r;
        float* cp = d.C + (size_t)m * d.ldc + tx * 8;
        *reinterpret_cast<float4*>(cp)     = make_float4(acc[r][0], acc[r][1], acc[r][2], acc[r][3]);
        *reinterpret_cast<float4*>(cp + 4) = make_float4(acc[r][4], acc[r][5], acc[r][6], acc[r][7]);
    }
}

// ---------------- GRU gate combine (sums GI8 x8 + GH4 x4 partials) ---------
__global__ void k_combine() {
    int idx = blockIdx.x * 256 + threadIdx.x;
    int b = idx >> 10, m = idx & 1023;
    const float* b_ih = g_ptr.w[3];
    const float* b_hh = g_ptr.w[4];
    int o = b * 3072;
    float ir = g_GIE[o + m] + b_ih[m];
    float iz = g_GIE[o + m + 1024] + b_ih[m + 1024];
    float in = g_GIE[o + m + 2048] + b_ih[m + 2048];
#pragma unroll
    for (int p = 0; p < 8; p++) {
        ir += g_GI8[p][o + m];
        iz += g_GI8[p][o + m + 1024];
        in += g_GI8[p][o + m + 2048];
    }
    float hr = b_hh[m], hz = b_hh[m + 1024], hn = b_hh[m + 2048];
#pragma unroll
    for (int p = 0; p < 4; p++) {
        hr += g_GH4[p][o + m];
        hz += g_GH4[p][o + m + 1024];
        hn += g_GH4[p][o + m + 2048];
    }
    float r = 1.f / (1.f + expf(-(ir + hr)));
    float z = 1.f / (1.f + expf(-(iz + hz)));
    float n = tanhf(fmaf(r, hn, in));
    float h = g_H[idx];
    g_H[idx] = fmaf(z, h - n, n);
}

// ---- gen_s: finalize row i + sample; 8 elems/thread for threefry ILP ------
__global__ __launch_bounds__(256) void k_gen_s(int i) {
    int j  = blockIdx.x >> 6;
    int b  = ((blockIdx.x & 63) << 1) + (threadIdx.x >> 7);
    int e  = (threadIdx.x & 127) << 3;
    uint2 kk = step_key(i);
    size_t off = (size_t)(j * cB + b) * cE + e;
    float4 mu0, mu1, sg0, sg1;
    if (j == i) {
        int q = b * 1024 + e;
        mu0 = *reinterpret_cast<const float4*>(g_ptr.w[6] + e);
        mu1 = *reinterpret_cast<const float4*>(g_ptr.w[6] + e + 4);
        sg0 = *reinterpret_cast<const float4*>(g_ptr.w[8] + e);
        sg1 = *reinterpret_cast<const float4*>(g_ptr.w[8] + e + 4);
#pragma unroll
        for (int p = 0; p < 4; p++) {
            float4 m0 = *reinterpret_cast<const float4*>(&g_MSP[p][q]);
            float4 m1 = *reinterpret_cast<const float4*>(&g_MSP[p][q + 4]);
            float4 s0 = *reinterpret_cast<const float4*>(&g_MSP[p + 4][q]);
            float4 s1 = *reinterpret_cast<const float4*>(&g_MSP[p + 4][q + 4]);
            mu0.x += m0.x; mu0.y += m0.y; mu0.z += m0.z; mu0.w += m0.w;
            mu1.x += m1.x; mu1.y += m1.y; mu1.z += m1.z; mu1.w += m1.w;
            sg0.x += s0.x; sg0.y += s0.y; sg0.z += s0.z; sg0.w += s0.w;
            sg1.x += s1.x; sg1.y += s1.y; sg1.z += s1.z; sg1.w += s1.w;
        }
        sg0.x = softplusf(sg0.x); sg0.y = softplusf(sg0.y);
        sg0.z = softplusf(sg0.z); sg0.w = softplusf(sg0.w);
        sg1.x = softplusf(sg1.x); sg1.y = softplusf(sg1.y);
        sg1.z = softplusf(sg1.z); sg1.w = softplusf(sg1.w);
        *reinterpret_cast<float4*>(g_MUS + off) = mu0;
        *reinterpret_cast<float4*>(g_MUS + off + 4) = mu1;
        *reinterpret_cast<float4*>(g_SIGS + off) = sg0;
        *reinterpret_cast<float4*>(g_SIGS + off + 4) = sg1;
    } else {
        mu0 = *reinterpret_cast<const float4*>(g_MUS + off);
        mu1 = *reinterpret_cast<const float4*>(g_MUS + off + 4);
        sg0 = *reinterpret_cast<const float4*>(g_SIGS + off);
        sg1 = *reinterpret_cast<const float4*>(g_SIGS + off + 4);
    }
    unsigned p = (unsigned)((b * cT + j) * cE + e);
    float ep[8];
#pragma unroll
    for (int u = 0; u < 8; u++) ep[u] = eps_at(kk.x, kk.y, p + u);
    float4 s0, s1;
    s0.x = fmaf(ep[0], sg0.x, mu0.x); s0.y = fmaf(ep[1], sg0.y, mu0.y);
    s0.z = fmaf(ep[2], sg0.z, mu0.z); s0.w = fmaf(ep[3], sg0.w, mu0.w);
    s1.x = fmaf(ep[4], sg1.x, mu1.x); s1.y = fmaf(ep[5], sg1.y, mu1.y);
    s1.z = fmaf(ep[6], sg1.z, mu1.z); s1.w = fmaf(ep[7], sg1.w, mu1.w);
    *reinterpret_cast<float4*>(g_S + off) = s0;
    *reinterpret_cast<float4*>(g_S + off + 4) = s1;
}

// finalize-only (step 127)
__global__ __launch_bounds__(256) void k_msfix(int i) {
    int b = blockIdx.x;
    int e = threadIdx.x << 2;
    int q = b * 1024 + e;
    size_t off = (size_t)(i * cB + b) * cE + e;
    float4 mu = *reinterpret_cast<const float4*>(g_ptr.w[6] + e);
    float4 sg = *reinterpret_cast<const float4*>(g_ptr.w[8] + e);
#pragma unroll
    for (int p = 0; p < 4; p++) {
        float4 mp = *reinterpret_cast<const float4*>(&g_MSP[p][q]);
        float4 sp = *reinterpret_cast<const float4*>(&g_MSP[p + 4][q]);
        mu.x += mp.x; mu.y += mp.y; mu.z += mp.z; mu.w += mp.w;
        sg.x += sp.x; sg.y += sp.y; sg.z += sp.z; sg.w += sp.w;
    }
    sg.x = softplusf(sg.x); sg.y = softplusf(sg.y);
    sg.z = softplusf(sg.z); sg.w = softplusf(sg.w);
    *reinterpret_cast<float4*>(g_MUS + off) = mu;
    *reinterpret_cast<float4*>(g_SIGS + off) = sg;
}

// ---------------- mega attention: 1 b per block, 128 blocks, 512 threads ----
// smem: zs[8192] (z half0 / final z) + z2[8192] (s staging, then z half1)
//       + w_s[1024] (scores/weights, then ctx)
__global__ __launch_bounds__(512) void k_attn(int i) {
    extern __shared__ float sm[];
    float* zs  = sm;            // 8192
    float* z2  = sm + 8192;     // 8192
    float* w_s = sm + 16384;    // 1024
    int b = blockIdx.x;
    int nj = i + 1;
    int tid = threadIdx.x;
    int w = tid >> 5, l = tid & 31;
    int hw = w & 7, jh = w >> 3;   // warp = (j-group jh, head hw)

    // ---- pass 1: scores; u in registers, 8 j-rows staged per round ----
    {
        float4 ureg[8];
        const float4* up = reinterpret_cast<const float4*>(g_U + (size_t)b * 8192 + hw * 1024);
#pragma unroll
        for (int k = 0; k < 8; k++) ureg[k] = up[l + 32 * k];

        for (int j0 = 0; j0 < nj; j0 += 8) {
#pragma unroll
            for (int r = 0; r < 4; r++) {
                int idx = tid + r * 512;         // 0..2047 float4
                int row = idx >> 8;              // 0..7
                int j = j0 + row;
                if (j < nj)
                    reinterpret_cast<float4*>(z2)[idx] =
                        reinterpret_cast<const float4*>(
                            g_S + (size_t)(j * cB + b) * cE)[idx & 255];
            }
            __syncthreads();
#pragma unroll
            for (int jr = 0; jr < 4; jr++) {
                int row = jh * 4 + jr;
                int j = j0 + row;
                if (j < nj) {
                    const float4* sv4 = reinterpret_cast<const float4*>(z2 + row * 1024);
                    float acc = 0.f;
#pragma unroll
                    for (int k = 0; k < 8; k++) {
                        float4 sv = sv4[l + 32 * k];
                        acc = fmaf(sv.x, ureg[k].x, acc); acc = fmaf(sv.y, ureg[k].y, acc);
                        acc = fmaf(sv.z, ureg[k].z, acc); acc = fmaf(sv.w, ureg[k].w, acc);
                    }
#pragma unroll
                    for (int o = 16; o; o >>= 1) acc += __shfl_xor_sync(0xffffffffu, acc, o);
                    if (l == 0) w_s[hw * 128 + j] = acc * 0.125f;   // 1/sqrt(64)
                }
            }
            __syncthreads();
        }
    }

    // ---- softmax per head (warps 0..7) ----
    if (w < 8) {
        float v[4];
#pragma unroll
        for (int cc = 0; cc < 4; cc++) {
            int j = l + 32 * cc;
            v[cc] = (j < nj) ? w_s[w * 128 + j] : -3.0e38f;
        }
        float m = fmaxf(fmaxf(v[0], v[1]), fmaxf(v[2], v[3]));
#pragma unroll
        for (int o = 16; o; o >>= 1) m = fmaxf(m, __shfl_xor_sync(0xffffffffu, m, o));
        float e[4], sum = 0.f;
#pragma unroll
        for (int cc = 0; cc < 4; cc++) {
            int j = l + 32 * cc;
            e[cc] = (j < nj) ? expf(v[cc] - m) : 0.f;
            sum += e[cc];
        }
#pragma unroll
        for (int o = 16; o; o >>= 1) sum += __shfl_xor_sync(0xffffffffu, sum, o);
        float inv = 1.f / sum;
#pragma unroll
        for (int cc = 0; cc < 4; cc++) {
            int j = l + 32 * cc;
            if (j < nj) w_s[w * 128 + j] = e[cc] * inv;
        }
    }
    __syncthreads();

    // ---- pass 2: z[h][e] = sum_j w*s, j-range split across 2 groups -------
    {
        int jg = tid >> 8;                 // 0/1
        int e0 = (tid & 255) << 2;         // 4 e's
        float za[8][4];
#pragma unroll
        for (int h = 0; h < 8; h++)
#pragma unroll
            for (int u = 0; u < 4; u++) za[h][u] = 0.f;
        for (int j = jg; j < nj; j += 2) {
            float4 sv = *reinterpret_cast<const float4*>(g_S + (size_t)(j * cB + b) * cE + e0);
#pragma unroll
            for (int h = 0; h < 8; h++) {
                float wj = w_s[h * 128 + j];
                za[h][0] = fmaf(wj, sv.x, za[h][0]);
                za[h][1] = fmaf(wj, sv.y, za[h][1]);
                za[h][2] = fmaf(wj, sv.z, za[h][2]);
                za[h][3] = fmaf(wj, sv.w, za[h][3]);
            }
        }
        __syncthreads();   // staging + w_s reads complete
        float* dst = jg ? z2 : zs;
#pragma unroll
        for (int h = 0; h < 8; h++)
            *reinterpret_cast<float4*>(dst + h * 1024 + e0) =
                make_float4(za[h][0], za[h][1], za[h][2], za[h][3]);
    }
    __syncthreads();
    // reduce the two j-halves into zs
    {
#pragma unroll
        for (int r = 0; r < 4; r++) {
            int idx = tid + r * 512;       // float4 index, 2048 total
            float4 a = reinterpret_cast<float4*>(zs)[idx];
            float4 c = reinterpret_cast<float4*>(z2)[idx];
            reinterpret_cast<float4*>(zs)[idx] =
                make_float4(a.x + c.x, a.y + c.y, a.z + c.z, a.w + c.w);
        }
    }
    __syncthreads();

    // ---- pass 3: ctx[c] = sum_e z[h(c)][e] Wv[e][c] + bv[c], c = tid ------
    {
        int c = tid;
        int h = c >> 6;
        const float* zrow = zs + h * 1024;
        const float* Wv = g_ptr.w[13];
        float a0 = 0.f, a1 = 0.f;
        for (int e = 0; e < 1024; e += 2) {
            a0 = fmaf(zrow[e],     Wv[(size_t)e * 512 + c],       a0);
            a1 = fmaf(zrow[e + 1], Wv[(size_t)(e + 1) * 512 + c], a1);
        }
        float ctx = a0 + a1 + g_ptr.w[14][c];
        __syncthreads();   // w_s weight reads (pass2) complete
        w_s[c] = ctx;
    }
    __syncthreads();

    // ---- pass 4: X[b, E+e'] = sum_c ctx[c] Wo[c][e'] + bo[e'] -------------
    {
        int e0 = tid << 1;
        const float* Wo = g_ptr.w[15];
        float a0 = 0.f, a1 = 0.f, b0 = 0.f, b1 = 0.f;
        for (int c = 0; c < 512; c += 2) {
            float cv0 = w_s[c], cv1 = w_s[c + 1];
            float2 w0 = *reinterpret_cast<const float2*>(Wo + (size_t)c * 1024 + e0);
            float2 w1 = *reinterpret_cast<const float2*>(Wo + (size_t)(c + 1) * 1024 + e0);
            a0 = fmaf(cv0, w0.x, a0); a1 = fmaf(cv0, w0.y, a1);
            b0 = fmaf(cv1, w1.x, b0); b1 = fmaf(cv1, w1.y, b1);
        }
        float2 bo2 = *reinterpret_cast<const float2*>(g_ptr.w[16] + e0);
        *reinterpret_cast<float2*>(g_X + b * 2048 + 1024 + e0) =
            make_float2(a0 + b0 + bo2.x, a1 + b1 + bo2.y);
    }
}

// ---------------- final output (B,T,E): step-127 noise ----------------
__global__ __launch_bounds__(256) void k_genout(float* __restrict__ out) {
    int j = blockIdx.x >> 6;
    int b = ((blockIdx.x & 63) << 1) + (threadIdx.x >> 7);
    int e = (threadIdx.x & 127) << 3;
    uint2 kk = step_key(cT - 1);
    size_t off = (size_t)(j * cB + b) * cE + e;
    float4 mu0 = *reinterpret_cast<const float4*>(g_MUS + off);
    float4 mu1 = *reinterpret_cast<const float4*>(g_MUS + off + 4);
    float4 sg0 = *reinterpret_cast<const float4*>(g_SIGS + off);
    float4 sg1 = *reinterpret_cast<const float4*>(g_SIGS + off + 4);
    unsigned p = (unsigned)((b * cT + j) * cE + e);
    float ep[8];
#pragma unroll
    for (int u = 0; u < 8; u++) ep[u] = eps_at(kk.x, kk.y, p + u);
    float4 s0, s1;
    s0.x = fmaf(ep[0], sg0.x, mu0.x); s0.y = fmaf(ep[1], sg0.y, mu0.y);
    s0.z = fmaf(ep[2], sg0.z, mu0.z); s0.w = fmaf(ep[3], sg0.w, mu0.w);
    s1.x = fmaf(ep[4], sg1.x, mu1.x); s1.y = fmaf(ep[5], sg1.y, mu1.y);
    s1.z = fmaf(ep[6], sg1.z, mu1.z); s1.w = fmaf(ep[7], sg1.w, mu1.w);
    *reinterpret_cast<float4*>(out + p) = s0;
    *reinterpret_cast<float4*>(out + p + 4) = s1;
}

// ---------------- host side ----------------
extern "C" void kernel_launch(void* const* d_in, const int* in_sizes, int n_in,
                              void* d_out, int out_size) {
    Ptrs P;
    for (int k = 0; k < 17; k++) P.w[k] = (const float*)d_in[k];
    float* out = (float*)d_out;

    constexpr int ATTN_SMEM = (8192 + 8192 + 1024) * 4;   // 69632 B
    cudaFuncSetAttribute(k_attn, cudaFuncAttributeMaxDynamicSharedMemorySize, ATTN_SMEM);

    k_setup<<<1, 1>>>(P);
    k_init<<<6144, 256>>>();
    k_gemm<<<dim3(1, 48, 1), 128>>>(SEL_EB, 0);      // encs half of gi (once)

    for (int i = 0; i < cT; i++) {
        k_gemm<<<dim3(1, 48, 8), 128>>>(SEL_GIC, i); // ctx-half gi, ksplit8
        k_combine<<<512, 256>>>();                   // h update (uses prev GH4)
        k_gemm<<<dim3(1, 80, 4), 128>>>(SEL_HMS, i); // h@[W_hh|W_mu|W_sig]

        if (i < cT - 1) {
            k_gen_s<<<(i + 1) * 64, 256>>>(i);       // finalize mu/sig row i + sample S
            k_gemm<<<dim3(1, 8, 4), 128>>>(SEL_QB, i);
            k_gemm<<<dim3(1, 16, 8), 128>>>(SEL_UB, i);
            k_attn<<<128, 512, ATTN_SMEM>>>(i);
        } else {
            k_msfix<<<cB, 256>>>(i);
        }
    }

    k_genout<<<cT * 64, 256>>>(out);
}

// round 15
// speedup vs baseline: 1.2482x; 1.1444x over previous
#include <cuda_runtime.h>
#include <cstdint>
#include <cmath>

// ---------------- problem constants ----------------
constexpr int cB = 128, cT = 128, cE = 1024, cH = 1024, cNH = 8, cA = 64;
constexpr int cKV = cNH * cA;          // 512
constexpr int BE  = cB * cE;           // 131072

// ---------------- persistent device scratch ----------------
__device__ float g_MUS [cT * BE];          // (T,B,E)
__device__ float g_SIGS[cT * BE];          // (T,B,E)
__device__ float g_S   [cT * BE];          // (T,B,E)
__device__ float g_CTX [cB * cKV];         // per-step attention context (pre-Wo)
__device__ float g_H   [cB * cH];
__device__ float g_GIE [cB * 3072];        // encs @ W_ih[:, :E]^T (once)
__device__ float g_GI8 [8][cB * 3072];     // ctx gi partials (ksplit8 over 512)
__device__ float g_GH4 [4][cB * 3072];     // gh partials (ksplit4)
__device__ float g_MSP [8][cB * cE];       // mu partials [0..3], sig partials [4..7]
__device__ float g_QP  [4][cB * cKV];      // q partials (ksplit4)
__device__ float g_U   [cB * cNH * cE];    // (b,h,e)
__device__ float g_WC  [512 * 3072];       // W_o @ W_ih[:,E:]^T  (once)
__device__ float g_BC  [3072];             // b_o @ W_ih[:,E:]^T  (once)

struct Ptrs { const float* w[17]; };
__device__ Ptrs g_ptr;

// ---------------- threefry2x32 (jax-exact bits) ----------------
__device__ __forceinline__ uint2 tf2x32(unsigned k0, unsigned k1, unsigned x0, unsigned x1) {
    unsigned k2 = k0 ^ k1 ^ 0x1BD11BDAu;
    x0 += k0; x1 += k1;
#define TFR(r) x0 += x1; x1 = __funnelshift_l(x1, x1, r); x1 ^= x0;
    TFR(13) TFR(15) TFR(26) TFR(6)   x0 += k1; x1 += k2 + 1u;
    TFR(17) TFR(29) TFR(16) TFR(24)  x0 += k2; x1 += k0 + 2u;
    TFR(13) TFR(15) TFR(26) TFR(6)   x0 += k0; x1 += k1 + 3u;
    TFR(17) TFR(29) TFR(16) TFR(24)  x0 += k1; x1 += k2 + 4u;
    TFR(13) TFR(15) TFR(26) TFR(6)   x0 += k2; x1 += k0 + 5u;
#undef TFR
    return make_uint2(x0, x1);
}
__device__ __forceinline__ uint2 step_key(int i) { return tf2x32(0u, 1234u, 0u, (unsigned)i); }

// bits -> N(0,1): jax _uniform + sqrt(2)*erf_inv (Giles poly), fast-log variant
__device__ __forceinline__ float tf_normal(unsigned bits) {
    float f = __uint_as_float((bits >> 9) | 0x3f800000u) - 1.0f;
    float u = fmaf(f, 2.0f, -0.99999994f);
    u = fmaxf(u, -0.99999994f);
    float w = -__logf(fmaf(-u, u, 1.0f));
    float p;
    if (w < 5.0f) {
        w -= 2.5f;
        p = 2.81022636e-08f;
        p = fmaf(p, w, 3.43273939e-07f);
        p = fmaf(p, w, -3.5233877e-06f);
        p = fmaf(p, w, -4.39150654e-06f);
        p = fmaf(p, w, 0.00021858087f);
        p = fmaf(p, w, -0.00125372503f);
        p = fmaf(p, w, -0.00417768164f);
        p = fmaf(p, w, 0.246640727f);
        p = fmaf(p, w, 1.50140941f);
    } else {
        w = sqrtf(w) - 3.0f;
        p = -0.000200214257f;
        p = fmaf(p, w, 0.000100950558f);
        p = fmaf(p, w, 0.00134934322f);
        p = fmaf(p, w, -0.00367342844f);
        p = fmaf(p, w, 0.00573950773f);
        p = fmaf(p, w, -0.0076224613f);
        p = fmaf(p, w, 0.00943887047f);
        p = fmaf(p, w, 1.00167406f);
        p = fmaf(p, w, 2.83297682f);
    }
    return 1.4142135623730951f * (p * u);
}
__device__ __forceinline__ float eps_at(unsigned k0, unsigned k1, unsigned idx) {
    uint2 r = tf2x32(k0, k1, 0u, idx);
    return tf_normal(r.x ^ r.y);
}
__device__ __forceinline__ float softplusf(float x) {
    return fmaxf(x, 0.f) + log1pf(expf(-fabsf(x)));
}

// ---------------- setup (g_ptr + bias_c) + init ----------------
__global__ void k_setup(Ptrs p) {
    int idx = blockIdx.x * 256 + threadIdx.x;
    if (idx == 0) g_ptr = p;
    if (idx < 3072) {
        const float* bo = p.w[16];
        const float* wih = p.w[1] + (size_t)idx * 2048 + 1024;
        float a0 = 0.f, a1 = 0.f;
        for (int e = 0; e < 1024; e += 2) {
            a0 = fmaf(bo[e], wih[e], a0);
            a1 = fmaf(bo[e + 1], wih[e + 1], a1);
        }
        g_BC[idx] = a0 + a1;
    }
}
__global__ void k_init() {
    int idx = blockIdx.x * 256 + threadIdx.x;
    if (idx < cB * cH) g_H[idx] = 0.f;
    if (idx < cB * cKV) g_CTX[idx] = 0.f;
    if (idx < 4 * cB * 3072) reinterpret_cast<float*>(g_GH4)[idx] = 0.f;  // h0=0 -> gh=0
}

// ---- SGEMM: BM=128/block-row, BN=64, BK=8, 128 thr, 8x8, dbl-buf ----------
enum { SEL_EB = 0, SEL_WC, SEL_GIC, SEL_HMS, SEL_QB, SEL_UB };

struct GD {
    const float* A; const float* Bm; float* C; const float* qbias;
    int lda, ldb, ldc, K, transB, qsum;
};

__device__ __forceinline__ GD get_desc(int sel, int y, int z, int i) {
    GD d; d.qbias = nullptr; d.transB = 0; d.qsum = 0;
    switch (sel) {
    case SEL_EB:   // encs @ W_ih[:, :E]^T ; y in [0,48)
        d.A = g_ptr.w[0]; d.lda = 1024; d.K = 1024;
        d.Bm = g_ptr.w[1] + (size_t)(y * 64) * 2048; d.ldb = 2048; d.transB = 1;
        d.C = g_GIE + y * 64; d.ldc = 3072; break;
    case SEL_WC:   // W_o @ W_ih[:,E:]^T ; M=512 (grid.x=4), y in [0,48)
        d.A = g_ptr.w[15]; d.lda = 1024; d.K = 1024;
        d.Bm = g_ptr.w[1] + 1024 + (size_t)(y * 64) * 2048; d.ldb = 2048; d.transB = 1;
        d.C = g_WC + y * 64; d.ldc = 3072; break;
    case SEL_GIC:  // ctx @ Wcomb ; ksplit8 over K=512 (z), y in [0,48)
        d.A = g_CTX + z * 64; d.lda = 512; d.K = 64;
        d.Bm = g_WC + (size_t)(z * 64) * 3072 + y * 64; d.ldb = 3072;
        d.C = g_GI8[z] + y * 64; d.ldc = 3072; break;
    case SEL_HMS:  // h @ [W_hh^T | W_mu | W_sig] ; ksplit4 (z), y in [0,80)
        d.A = g_H + z * 256; d.lda = 1024; d.K = 256;
        if (y < 48) {
            d.Bm = g_ptr.w[2] + z * 256 + (size_t)(y * 64) * 1024; d.ldb = 1024; d.transB = 1;
            d.C = g_GH4[z] + y * 64; d.ldc = 3072;
        } else if (y < 64) {
            int yy = y - 48;
            d.Bm = g_ptr.w[5] + (size_t)(z * 256) * 1024 + yy * 64; d.ldb = 1024;
            d.C = g_MSP[z] + yy * 64; d.ldc = 1024;
        } else {
            int yy = y - 64;
            d.Bm = g_ptr.w[7] + (size_t)(z * 256) * 1024 + yy * 64; d.ldb = 1024;
            d.C = g_MSP[4 + z] + yy * 64; d.ldc = 1024;
        }
        break;
    case SEL_QB:   // s_i @ W_q ; ksplit4 (z), y in [0,8)
        d.A = g_S + (size_t)i * BE + z * 256; d.lda = 1024; d.K = 256;
        d.Bm = g_ptr.w[9] + (size_t)(z * 256) * 512 + y * 64; d.ldb = 512;
        d.C = g_QP[z] + y * 64; d.ldc = 512; break;
    default:       // SEL_UB: u_h = (sum 4 q-partials + b_q) @ W_k_h^T ; z=head, y in [0,16)
        d.qsum = 1;
        d.A = g_QP[0] + z * 64; d.lda = 512; d.K = 64;
        d.qbias = g_ptr.w[10] + z * 64;
        d.Bm = g_ptr.w[11] + z * 64 + (size_t)(y * 64) * 512; d.ldb = 512; d.transB = 1;
        d.C = g_U + z * 1024 + y * 64; d.ldc = 8192; break;
    }
    return d;
}

__global__ __launch_bounds__(128) void k_gemm(int sel, int i) {
    GD d = get_desc(sel, blockIdx.y, blockIdx.z, i);
    int m0 = blockIdx.x * 128;

    __shared__ __align__(16) float As[2][8][132];
    __shared__ __align__(16) float Bs[2][8][68];

    int tid = threadIdx.x;
    int tx = tid & 7, ty = tid >> 3;

    float acc[8][8];
#pragma unroll
    for (int r = 0; r < 8; r++)
#pragma unroll
        for (int c = 0; c < 8; c++) acc[r][c] = 0.f;

    float4 va[2]; float4 vb;
    int arow = tid >> 1, akc = (tid & 1) << 2;
    int bkk = tid >> 4, bnc = (tid & 15) << 2;
    int bnn = tid >> 1, bkc = (tid & 1) << 2;

    auto loadT = [&](int k0) {
#pragma unroll
        for (int r = 0; r < 2; r++) {
            const float* ap = d.A + (size_t)(m0 + arow + r * 64) * d.lda + k0 + akc;
            if (!d.qsum) {
                va[r] = *reinterpret_cast<const float4*>(ap);
            } else {
                float4 v0 = *reinterpret_cast<const float4*>(ap);
                float4 v1 = *reinterpret_cast<const float4*>(ap + 65536);
                float4 v2 = *reinterpret_cast<const float4*>(ap + 131072);
                float4 v3 = *reinterpret_cast<const float4*>(ap + 196608);
                float4 bb = *reinterpret_cast<const float4*>(d.qbias + k0 + akc);
                va[r].x = v0.x + v1.x + v2.x + v3.x + bb.x;
                va[r].y = v0.y + v1.y + v2.y + v3.y + bb.y;
                va[r].z = v0.z + v1.z + v2.z + v3.z + bb.z;
                va[r].w = v0.w + v1.w + v2.w + v3.w + bb.w;
            }
        }
        if (!d.transB)
            vb = *reinterpret_cast<const float4*>(d.Bm + (size_t)(k0 + bkk) * d.ldb + bnc);
        else
            vb = *reinterpret_cast<const float4*>(d.Bm + (size_t)bnn * d.ldb + k0 + bkc);
    };
    auto storeT = [&](int cur) {
#pragma unroll
        for (int r = 0; r < 2; r++) {
            int row = arow + r * 64;
            As[cur][akc + 0][row] = va[r].x; As[cur][akc + 1][row] = va[r].y;
            As[cur][akc + 2][row] = va[r].z; As[cur][akc + 3][row] = va[r].w;
        }
        if (!d.transB) {
            *reinterpret_cast<float4*>(&Bs[cur][bkk][bnc]) = vb;
        } else {
            Bs[cur][bkc + 0][bnn] = vb.x; Bs[cur][bkc + 1][bnn] = vb.y;
            Bs[cur][bkc + 2][bnn] = vb.z; Bs[cur][bkc + 3][bnn] = vb.w;
        }
    };

    int nt = d.K >> 3;
    loadT(0);
    int cur = 0;
    for (int t = 0; t < nt; t++) {
        storeT(cur);
        __syncthreads();
        if (t + 1 < nt) loadT((t + 1) << 3);
#pragma unroll
        for (int kk = 0; kk < 8; kk++) {
            float4 a0 = *reinterpret_cast<const float4*>(&As[cur][kk][ty * 8]);
            float4 a1 = *reinterpret_cast<const float4*>(&As[cur][kk][ty * 8 + 4]);
            float4 b0 = *reinterpret_cast<const float4*>(&Bs[cur][kk][tx * 8]);
            float4 b1 = *reinterpret_cast<const float4*>(&Bs[cur][kk][tx * 8 + 4]);
            float af[8] = {a0.x, a0.y, a0.z, a0.w, a1.x, a1.y, a1.z, a1.w};
            float bf[8] = {b0.x, b0.y, b0.z, b0.w, b1.x, b1.y, b1.z, b1.w};
#pragma unroll
            for (int r = 0; r < 8; r++)
#pragma unroll
                for (int c = 0; c < 8; c++) acc[r][c] = fmaf(af[r], bf[c], acc[r][c]);
        }
        cur ^= 1;
    }

#pragma unroll
    for (int r = 0; r < 8; r++) {
        int m = m0 + ty * 8 + r;
        float* cp = d.C + (size_t)m * d.ldc + tx * 8;
        *reinterpret_cast<float4*>(cp)     = make_float4(acc[r][0], acc[r][1], acc[r][2], acc[r][3]);
        *reinterpret_cast<float4*>(cp + 4) = make_float4(acc[r][4], acc[r][5], acc[r][6], acc[r][7]);
    }
}

// ---------------- GRU gate combine (sums GI8 x8 + GH4 x4 partials + BC) ----
__global__ void k_combine() {
    int idx = blockIdx.x * 256 + threadIdx.x;
    int b = idx >> 10, m = idx & 1023;
    const float* b_ih = g_ptr.w[3];
    const float* b_hh = g_ptr.w[4];
    int o = b * 3072;
    float ir = g_GIE[o + m] + b_ih[m] + g_BC[m];
    float iz = g_GIE[o + m + 1024] + b_ih[m + 1024] + g_BC[m + 1024];
    float in = g_GIE[o + m + 2048] + b_ih[m + 2048] + g_BC[m + 2048];
#pragma unroll
    for (int p = 0; p < 8; p++) {
        ir += g_GI8[p][o + m];
        iz += g_GI8[p][o + m + 1024];
        in += g_GI8[p][o + m + 2048];
    }
    float hr = b_hh[m], hz = b_hh[m + 1024], hn = b_hh[m + 2048];
#pragma unroll
    for (int p = 0; p < 4; p++) {
        hr += g_GH4[p][o + m];
        hz += g_GH4[p][o + m + 1024];
        hn += g_GH4[p][o + m + 2048];
    }
    float r = 1.f / (1.f + expf(-(ir + hr)));
    float z = 1.f / (1.f + expf(-(iz + hz)));
    float n = tanhf(fmaf(r, hn, in));
    float h = g_H[idx];
    g_H[idx] = fmaf(z, h - n, n);
}

// ---- gen_s: finalize row i + sample; 8 elems/thread for threefry ILP ------
__global__ __launch_bounds__(256) void k_gen_s(int i) {
    int j  = blockIdx.x >> 6;
    int b  = ((blockIdx.x & 63) << 1) + (threadIdx.x >> 7);
    int e  = (threadIdx.x & 127) << 3;
    uint2 kk = step_key(i);
    size_t off = (size_t)(j * cB + b) * cE + e;
    float4 mu0, mu1, sg0, sg1;
    if (j == i) {
        int q = b * 1024 + e;
        mu0 = *reinterpret_cast<const float4*>(g_ptr.w[6] + e);
        mu1 = *reinterpret_cast<const float4*>(g_ptr.w[6] + e + 4);
        sg0 = *reinterpret_cast<const float4*>(g_ptr.w[8] + e);
        sg1 = *reinterpret_cast<const float4*>(g_ptr.w[8] + e + 4);
#pragma unroll
        for (int p = 0; p < 4; p++) {
            float4 m0 = *reinterpret_cast<const float4*>(&g_MSP[p][q]);
            float4 m1 = *reinterpret_cast<const float4*>(&g_MSP[p][q + 4]);
            float4 s0 = *reinterpret_cast<const float4*>(&g_MSP[p + 4][q]);
            float4 s1 = *reinterpret_cast<const float4*>(&g_MSP[p + 4][q + 4]);
            mu0.x += m0.x; mu0.y += m0.y; mu0.z += m0.z; mu0.w += m0.w;
            mu1.x += m1.x; mu1.y += m1.y; mu1.z += m1.z; mu1.w += m1.w;
            sg0.x += s0.x; sg0.y += s0.y; sg0.z += s0.z; sg0.w += s0.w;
            sg1.x += s1.x; sg1.y += s1.y; sg1.z += s1.z; sg1.w += s1.w;
        }
        sg0.x = softplusf(sg0.x); sg0.y = softplusf(sg0.y);
        sg0.z = softplusf(sg0.z); sg0.w = softplusf(sg0.w);
        sg1.x = softplusf(sg1.x); sg1.y = softplusf(sg1.y);
        sg1.z = softplusf(sg1.z); sg1.w = softplusf(sg1.w);
        *reinterpret_cast<float4*>(g_MUS + off) = mu0;
        *reinterpret_cast<float4*>(g_MUS + off + 4) = mu1;
        *reinterpret_cast<float4*>(g_SIGS + off) = sg0;
        *reinterpret_cast<float4*>(g_SIGS + off + 4) = sg1;
    } else {
        mu0 = *reinterpret_cast<const float4*>(g_MUS + off);
        mu1 = *reinterpret_cast<const float4*>(g_MUS + off + 4);
        sg0 = *reinterpret_cast<const float4*>(g_SIGS + off);
        sg1 = *reinterpret_cast<const float4*>(g_SIGS + off + 4);
    }
    unsigned p = (unsigned)((b * cT + j) * cE + e);
    float ep[8];
#pragma unroll
    for (int u = 0; u < 8; u++) ep[u] = eps_at(kk.x, kk.y, p + u);
    float4 s0, s1;
    s0.x = fmaf(ep[0], sg0.x, mu0.x); s0.y = fmaf(ep[1], sg0.y, mu0.y);
    s0.z = fmaf(ep[2], sg0.z, mu0.z); s0.w = fmaf(ep[3], sg0.w, mu0.w);
    s1.x = fmaf(ep[4], sg1.x, mu1.x); s1.y = fmaf(ep[5], sg1.y, mu1.y);
    s1.z = fmaf(ep[6], sg1.z, mu1.z); s1.w = fmaf(ep[7], sg1.w, mu1.w);
    *reinterpret_cast<float4*>(g_S + off) = s0;
    *reinterpret_cast<float4*>(g_S + off + 4) = s1;
}

// finalize-only (step 127)
__global__ __launch_bounds__(256) void k_msfix(int i) {
    int b = blockIdx.x;
    int e = threadIdx.x << 2;
    int q = b * 1024 + e;
    size_t off = (size_t)(i * cB + b) * cE + e;
    float4 mu = *reinterpret_cast<const float4*>(g_ptr.w[6] + e);
    float4 sg = *reinterpret_cast<const float4*>(g_ptr.w[8] + e);
#pragma unroll
    for (int p = 0; p < 4; p++) {
        float4 mp = *reinterpret_cast<const float4*>(&g_MSP[p][q]);
        float4 sp = *reinterpret_cast<const float4*>(&g_MSP[p + 4][q]);
        mu.x += mp.x; mu.y += mp.y; mu.z += mp.z; mu.w += mp.w;
        sg.x += sp.x; sg.y += sp.y; sg.z += sp.z; sg.w += sp.w;
    }
    sg.x = softplusf(sg.x); sg.y = softplusf(sg.y);
    sg.z = softplusf(sg.z); sg.w = softplusf(sg.w);
    *reinterpret_cast<float4*>(g_MUS + off) = mu;
    *reinterpret_cast<float4*>(g_SIGS + off) = sg;
}

// ---------------- mega attention: 1 b per block, 128 blocks, 512 threads ----
// passes: scores -> softmax -> z -> ctx (written to g_CTX; no out-proj)
__global__ __launch_bounds__(512) void k_attn(int i) {
    extern __shared__ float sm[];
    float* zs  = sm;            // 8192
    float* z2  = sm + 8192;     // 8192 (staging, then z half1)
    float* w_s = sm + 16384;    // 1024
    int b = blockIdx.x;
    int nj = i + 1;
    int tid = threadIdx.x;
    int w = tid >> 5, l = tid & 31;
    int hw = w & 7, jh = w >> 3;

    // ---- pass 1: scores; u in registers, 8 j-rows staged per round ----
    {
        float4 ureg[8];
        const float4* up = reinterpret_cast<const float4*>(g_U + (size_t)b * 8192 + hw * 1024);
#pragma unroll
        for (int k = 0; k < 8; k++) ureg[k] = up[l + 32 * k];

        for (int j0 = 0; j0 < nj; j0 += 8) {
#pragma unroll
            for (int r = 0; r < 4; r++) {
                int idx = tid + r * 512;
                int row = idx >> 8;
                int j = j0 + row;
                if (j < nj)
                    reinterpret_cast<float4*>(z2)[idx] =
                        reinterpret_cast<const float4*>(
                            g_S + (size_t)(j * cB + b) * cE)[idx & 255];
            }
            __syncthreads();
#pragma unroll
            for (int jr = 0; jr < 4; jr++) {
                int row = jh * 4 + jr;
                int j = j0 + row;
                if (j < nj) {
                    const float4* sv4 = reinterpret_cast<const float4*>(z2 + row * 1024);
                    float acc = 0.f;
#pragma unroll
                    for (int k = 0; k < 8; k++) {
                        float4 sv = sv4[l + 32 * k];
                        acc = fmaf(sv.x, ureg[k].x, acc); acc = fmaf(sv.y, ureg[k].y, acc);
                        acc = fmaf(sv.z, ureg[k].z, acc); acc = fmaf(sv.w, ureg[k].w, acc);
                    }
#pragma unroll
                    for (int o = 16; o; o >>= 1) acc += __shfl_xor_sync(0xffffffffu, acc, o);
                    if (l == 0) w_s[hw * 128 + j] = acc * 0.125f;   // 1/sqrt(64)
                }
            }
            __syncthreads();
        }
    }

    // ---- softmax per head (warps 0..7) ----
    if (w < 8) {
        float v[4];
#pragma unroll
        for (int cc = 0; cc < 4; cc++) {
            int j = l + 32 * cc;
            v[cc] = (j < nj) ? w_s[w * 128 + j] : -3.0e38f;
        }
        float m = fmaxf(fmaxf(v[0], v[1]), fmaxf(v[2], v[3]));
#pragma unroll
        for (int o = 16; o; o >>= 1) m = fmaxf(m, __shfl_xor_sync(0xffffffffu, m, o));
        float e[4], sum = 0.f;
#pragma unroll
        for (int cc = 0; cc < 4; cc++) {
            int j = l + 32 * cc;
            e[cc] = (j < nj) ? expf(v[cc] - m) : 0.f;
            sum += e[cc];
        }
#pragma unroll
        for (int o = 16; o; o >>= 1) sum += __shfl_xor_sync(0xffffffffu, sum, o);
        float inv = 1.f / sum;
#pragma unroll
        for (int cc = 0; cc < 4; cc++) {
            int j = l + 32 * cc;
            if (j < nj) w_s[w * 128 + j] = e[cc] * inv;
        }
    }
    __syncthreads();

    // ---- pass 2: z[h][e] = sum_j w*s, j-range split across 2 groups -------
    {
        int jg = tid >> 8;
        int e0 = (tid & 255) << 2;
        float za[8][4];
#pragma unroll
        for (int h = 0; h < 8; h++)
#pragma unroll
            for (int u = 0; u < 4; u++) za[h][u] = 0.f;
        for (int j = jg; j < nj; j += 2) {
            float4 sv = *reinterpret_cast<const float4*>(g_S + (size_t)(j * cB + b) * cE + e0);
#pragma unroll
            for (int h = 0; h < 8; h++) {
                float wj = w_s[h * 128 + j];
                za[h][0] = fmaf(wj, sv.x, za[h][0]);
                za[h][1] = fmaf(wj, sv.y, za[h][1]);
                za[h][2] = fmaf(wj, sv.z, za[h][2]);
                za[h][3] = fmaf(wj, sv.w, za[h][3]);
            }
        }
        __syncthreads();
        float* dst = jg ? z2 : zs;
#pragma unroll
        for (int h = 0; h < 8; h++)
            *reinterpret_cast<float4*>(dst + h * 1024 + e0) =
                make_float4(za[h][0], za[h][1], za[h][2], za[h][3]);
    }
    __syncthreads();
    {
#pragma unroll
        for (int r = 0; r < 4; r++) {
            int idx = tid + r * 512;
            float4 a = reinterpret_cast<float4*>(zs)[idx];
            float4 c = reinterpret_cast<float4*>(z2)[idx];
            reinterpret_cast<float4*>(zs)[idx] =
                make_float4(a.x + c.x, a.y + c.y, a.z + c.z, a.w + c.w);
        }
    }
    __syncthreads();

    // ---- pass 3: ctx[c] = sum_e z[h(c)][e] Wv[e][c] + bv[c] -> g_CTX ------
    {
        int c = tid;
        int h = c >> 6;
        const float* zrow = zs + h * 1024;
        const float* Wv = g_ptr.w[13];
        float a0 = 0.f, a1 = 0.f;
        for (int e = 0; e < 1024; e += 2) {
            a0 = fmaf(zrow[e],     Wv[(size_t)e * 512 + c],       a0);
            a1 = fmaf(zrow[e + 1], Wv[(size_t)(e + 1) * 512 + c], a1);
        }
        g_CTX[b * cKV + c] = a0 + a1 + g_ptr.w[14][c];
    }
}

// ---------------- final output (B,T,E): step-127 noise ----------------
__global__ __launch_bounds__(256) void k_genout(float* __restrict__ out) {
    int j = blockIdx.x >> 6;
    int b = ((blockIdx.x & 63) << 1) + (threadIdx.x >> 7);
    int e = (threadIdx.x & 127) << 3;
    uint2 kk = step_key(cT - 1);
    size_t off = (size_t)(j * cB + b) * cE + e;
    float4 mu0 = *reinterpret_cast<const float4*>(g_MUS + off);
    float4 mu1 = *reinterpret_cast<const float4*>(g_MUS + off + 4);
    float4 sg0 = *reinterpret_cast<const float4*>(g_SIGS + off);
    float4 sg1 = *reinterpret_cast<const float4*>(g_SIGS + off + 4);
    unsigned p = (unsigned)((b * cT + j) * cE + e);
    float ep[8];
#pragma unroll
    for (int u = 0; u < 8; u++) ep[u] = eps_at(kk.x, kk.y, p + u);
    float4 s0, s1;
    s0.x = fmaf(ep[0], sg0.x, mu0.x); s0.y = fmaf(ep[1], sg0.y, mu0.y);
    s0.z = fmaf(ep[2], sg0.z, mu0.z); s0.w = fmaf(ep[3], sg0.w, mu0.w);
    s1.x = fmaf(ep[4], sg1.x, mu1.x); s1.y = fmaf(ep[5], sg1.y, mu1.y);
    s1.z = fmaf(ep[6], sg1.z, mu1.z); s1.w = fmaf(ep[7], sg1.w, mu1.w);
    *reinterpret_cast<float4*>(out + p) = s0;
    *reinterpret_cast<float4*>(out + p + 4) = s1;
}

// ---------------- host side ----------------
extern "C" void kernel_launch(void* const* d_in, const int* in_sizes, int n_in,
                              void* d_out, int out_size) {
    Ptrs P;
    for (int k = 0; k < 17; k++) P.w[k] = (const float*)d_in[k];
    float* out = (float*)d_out;

    constexpr int ATTN_SMEM = (8192 + 8192 + 1024) * 4;   // 69632 B
    cudaFuncSetAttribute(k_attn, cudaFuncAttributeMaxDynamicSharedMemorySize, ATTN_SMEM);

    k_setup<<<12, 256>>>(P);                          // g_ptr + bias_c
    k_init<<<6144, 256>>>();
    k_gemm<<<dim3(1, 48, 1), 128>>>(SEL_EB, 0);       // encs half of gi (once)
    k_gemm<<<dim3(4, 48, 1), 128>>>(SEL_WC, 0);       // Wcomb = W_o @ W_ih2^T (once)

    for (int i = 0; i < cT; i++) {
        k_gemm<<<dim3(1, 48, 8), 128>>>(SEL_GIC, i);  // ctx gi, K=512 ksplit8
        k_combine<<<512, 256>>>();                    // h update (uses prev GH4)
        k_gemm<<<dim3(1, 80, 4), 128>>>(SEL_HMS, i);  // h@[W_hh|W_mu|W_sig]

        if (i < cT - 1) {
            k_gen_s<<<(i + 1) * 64, 256>>>(i);        // finalize mu/sig row i + sample S
            k_gemm<<<dim3(1, 8, 4), 128>>>(SEL_QB, i);
            k_gemm<<<dim3(1, 16, 8), 128>>>(SEL_UB, i);
            k_attn<<<128, 512, ATTN_SMEM>>>(i);
        } else {
            k_msfix<<<cB, 256>>>(i);
        }
    }

    k_genout<<<cT * 64, 256>>>(out);
}